// round 5
// baseline (speedup 1.0000x reference)
#include <cuda_runtime.h>
#include <cuda_bf16.h>

// Problem constants (fixed for this dataset)
#define N_NODES 100000
#define N_EDGES 1200000
#define DIMF    64
#define LN_EPS  1e-5f
#define OUTW    384              // 2*(L+1)*D = 6*64

#define TILE    1024
#define N_TILES ((N_NODES + TILE - 1) / TILE)   // 98

// ---------------- device scratch (static, allowed) ----------------
__device__ int   g_count[N_NODES];            // histogram, then scatter cursor
__device__ int   g_row_ptr[N_NODES + 1];      // CSR by dst
__device__ int   g_col[N_EDGES];              // src ids grouped by dst
__device__ int   g_tile_sum[N_TILES];
__device__ int   g_tile_off[N_TILES];
__device__ float g_hn[N_NODES * DIMF];        // LN(feature)
// Interleaved per-node layout: [node][window][dim] -> 768 B contiguous per node
__device__ float g_h1[N_NODES * 3 * DIMF];    // after layer 1 (gathered by layer 2)

// ---------------- helpers ----------------
__device__ __forceinline__ void warp_reduce2(float& s, float& sq) {
#pragma unroll
    for (int o = 16; o; o >>= 1) {
        s  += __shfl_xor_sync(0xFFFFFFFFu, s,  o);
        sq += __shfl_xor_sync(0xFFFFFFFFu, sq, o);
    }
}

// LayerNorm(64) + ReLU on a warp-held row (float2 per lane); returns values.
__device__ __forceinline__ float2 ln_relu(float x, float y) {
    float s  = x + y;
    float sq = x * x + y * y;
    warp_reduce2(s, sq);
    float mean = s * (1.0f / 64.0f);
    float var  = fmaxf(sq * (1.0f / 64.0f) - mean * mean, 0.0f);
    float inv  = rsqrtf(var + LN_EPS);
    float2 o;
    o.x = fmaxf((x - mean) * inv, 0.0f);
    o.y = fmaxf((y - mean) * inv, 0.0f);
    return o;
}

// ---------------- kernels ----------------

// hn = LayerNorm(feature). Also writes output seg0 (hn) and seg3 (hn*(1-.5*(m1+m2))).
__global__ void ln_input_kernel(const float* __restrict__ feat,
                                const int* __restrict__ age,
                                float* __restrict__ out) {
    int v    = (blockIdx.x * blockDim.x + threadIdx.x) >> 5;
    int lane = threadIdx.x & 31;
    if (v >= N_NODES) return;
    float2 f = reinterpret_cast<const float2*>(feat)[v * 32 + lane];
    float s  = f.x + f.y;
    float sq = f.x * f.x + f.y * f.y;
    warp_reduce2(s, sq);
    float mean = s * (1.0f / 64.0f);
    float var  = fmaxf(sq * (1.0f / 64.0f) - mean * mean, 0.0f);
    float inv  = rsqrtf(var + LN_EPS);
    float2 o;
    o.x = (f.x - mean) * inv;
    o.y = (f.y - mean) * inv;
    reinterpret_cast<float2*>(g_hn)[v * 32 + lane] = o;

    int ag = __ldg(&age[v]);
    float scale = 1.0f - 0.5f * (float)((ag >= 1) + (ag >= 2));
    float2* orow = reinterpret_cast<float2*>(out + v * OUTW);
    orow[lane] = o;                                         // seg0: cols [0,64)
    float2 o3; o3.x = o.x * scale; o3.y = o.y * scale;
    orow[96 + lane] = o3;                                   // seg3: cols [192,256)
}

__global__ void hist_kernel(const int* __restrict__ dst) {
    int i = blockIdx.x * blockDim.x + threadIdx.x;
    if (i < N_EDGES) atomicAdd(&g_count[dst[i]], 1);
}

// --- hierarchical exclusive scan over g_count -> g_row_ptr ---
__global__ void scan_tiles_kernel() {
    __shared__ int warp_sums[32];
    int tile = blockIdx.x;
    int t    = threadIdx.x;           // 0..1023
    int idx  = tile * TILE + t;
    int lane = t & 31;
    int wid  = t >> 5;
    int v = (idx < N_NODES) ? g_count[idx] : 0;
    int incl = v;
#pragma unroll
    for (int o = 1; o < 32; o <<= 1) {
        int n = __shfl_up_sync(0xFFFFFFFFu, incl, o);
        if (lane >= o) incl += n;
    }
    if (lane == 31) warp_sums[wid] = incl;
    __syncthreads();
    if (wid == 0) {
        int ws = warp_sums[lane];
        int wi = ws;
#pragma unroll
        for (int o = 1; o < 32; o <<= 1) {
            int n = __shfl_up_sync(0xFFFFFFFFu, wi, o);
            if (lane >= o) wi += n;
        }
        warp_sums[lane] = wi - ws;   // exclusive warp offsets
        if (lane == 31) g_tile_sum[tile] = wi;   // tile total
    }
    __syncthreads();
    int excl = incl - v + warp_sums[wid];
    if (idx < N_NODES) g_row_ptr[idx] = excl;    // tile-local for now
}

__global__ void scan_mid_kernel() {
    __shared__ int sh[128];
    int t = threadIdx.x;   // 0..127
    int v = (t < N_TILES) ? g_tile_sum[t] : 0;
    sh[t] = v;
    __syncthreads();
#pragma unroll
    for (int o = 1; o < 128; o <<= 1) {
        int add = (t >= o) ? sh[t - o] : 0;
        __syncthreads();
        sh[t] += add;
        __syncthreads();
    }
    if (t < N_TILES) g_tile_off[t] = sh[t] - v;
    if (t == 127) g_row_ptr[N_NODES] = sh[127];
}

__global__ void scan_add_kernel() {
    int idx = blockIdx.x * blockDim.x + threadIdx.x;
    if (idx < N_NODES) {
        int r = g_row_ptr[idx] + g_tile_off[idx / TILE];
        g_row_ptr[idx] = r;
        g_count[idx]   = r;     // cursor for scatter
    }
}

__global__ void scatter_kernel(const int* __restrict__ src, const int* __restrict__ dst) {
    int i = blockIdx.x * blockDim.x + threadIdx.x;
    if (i < N_EDGES) {
        int pos = atomicAdd(&g_count[dst[i]], 1);
        g_col[pos] = src[i];
    }
}

// Layer 1: gather hn rows + age, 3 masked accumulators, fused LN+ReLU.
// Writes g_h1 (for layer 2) AND output seg1/seg4 directly.
__global__ void layer1_kernel(const int* __restrict__ age, float* __restrict__ out) {
    int v    = (blockIdx.x * blockDim.x + threadIdx.x) >> 5;
    int lane = threadIdx.x & 31;
    if (v >= N_NODES) return;
    int beg = g_row_ptr[v];
    int end = g_row_ptr[v + 1];
    float a0x = 0.f, a0y = 0.f, a1x = 0.f, a1y = 0.f, a2x = 0.f, a2y = 0.f;
    const float2* hn2 = reinterpret_cast<const float2*>(g_hn);
    for (int e = beg; e < end; e += 4) {
        int r = end - e;
        int u0 = g_col[e];
        int u1 = (r > 1) ? g_col[e + 1] : u0;
        int u2 = (r > 2) ? g_col[e + 2] : u0;
        int u3 = (r > 3) ? g_col[e + 3] : u0;
        float2 h0 = hn2[u0 * 32 + lane];
        float2 h1 = hn2[u1 * 32 + lane];
        float2 h2 = hn2[u2 * 32 + lane];
        float2 h3 = hn2[u3 * 32 + lane];
        int g0 = __ldg(&age[u0]);
        int g1 = __ldg(&age[u1]);
        int g2 = __ldg(&age[u2]);
        int g3 = __ldg(&age[u3]);
        a0x += h0.x; a0y += h0.y;
        if (g0 >= 1) { a1x += h0.x; a1y += h0.y; }
        if (g0 >= 2) { a2x += h0.x; a2y += h0.y; }
        if (r > 1) {
            a0x += h1.x; a0y += h1.y;
            if (g1 >= 1) { a1x += h1.x; a1y += h1.y; }
            if (g1 >= 2) { a2x += h1.x; a2y += h1.y; }
        }
        if (r > 2) {
            a0x += h2.x; a0y += h2.y;
            if (g2 >= 1) { a1x += h2.x; a1y += h2.y; }
            if (g2 >= 2) { a2x += h2.x; a2y += h2.y; }
        }
        if (r > 3) {
            a0x += h3.x; a0y += h3.y;
            if (g3 >= 1) { a1x += h3.x; a1y += h3.y; }
            if (g3 >= 2) { a2x += h3.x; a2y += h3.y; }
        }
    }
    float2 w0 = ln_relu(a0x, a0y);
    float2 w1 = ln_relu(a1x, a1y);
    float2 w2 = ln_relu(a2x, a2y);
    float2* h1row = reinterpret_cast<float2*>(&g_h1[v * 3 * DIMF]);
    h1row[lane]      = w0;
    h1row[32 + lane] = w1;
    h1row[64 + lane] = w2;
    float2* orow = reinterpret_cast<float2*>(out + v * OUTW);
    orow[32 + lane] = w0;                                   // seg1: cols [64,128)
    float2 d;
    d.x = w0.x - 0.5f * (w1.x + w2.x);
    d.y = w0.y - 0.5f * (w1.y + w2.y);
    orow[128 + lane] = d;                                   // seg4: cols [256,320)
}

// Layer 2: gather 3 contiguous window rows per src node (768 B block), 4-way batched.
// Writes output seg2/seg5 directly; no g_h2 array at all.
__global__ void layer2_kernel(float* __restrict__ out) {
    int v    = (blockIdx.x * blockDim.x + threadIdx.x) >> 5;
    int lane = threadIdx.x & 31;
    if (v >= N_NODES) return;
    int beg = g_row_ptr[v];
    int end = g_row_ptr[v + 1];
    float a0x = 0.f, a0y = 0.f, a1x = 0.f, a1y = 0.f, a2x = 0.f, a2y = 0.f;
    const float2* h1v = reinterpret_cast<const float2*>(g_h1);  // node stride = 96 float2
    for (int e = beg; e < end; e += 4) {
        int r = end - e;
        int u0 = g_col[e];
        int u1 = (r > 1) ? g_col[e + 1] : u0;
        int u2 = (r > 2) ? g_col[e + 2] : u0;
        int u3 = (r > 3) ? g_col[e + 3] : u0;
        int b0 = u0 * 96 + lane;
        int b1 = u1 * 96 + lane;
        int b2 = u2 * 96 + lane;
        int b3 = u3 * 96 + lane;
        float2 h00 = h1v[b0], h01 = h1v[b0 + 32], h02 = h1v[b0 + 64];
        float2 h10 = h1v[b1], h11 = h1v[b1 + 32], h12 = h1v[b1 + 64];
        float2 h20 = h1v[b2], h21 = h1v[b2 + 32], h22 = h1v[b2 + 64];
        float2 h30 = h1v[b3], h31 = h1v[b3 + 32], h32 = h1v[b3 + 64];
        a0x += h00.x; a0y += h00.y;
        a1x += h01.x; a1y += h01.y;
        a2x += h02.x; a2y += h02.y;
        if (r > 1) {
            a0x += h10.x; a0y += h10.y;
            a1x += h11.x; a1y += h11.y;
            a2x += h12.x; a2y += h12.y;
        }
        if (r > 2) {
            a0x += h20.x; a0y += h20.y;
            a1x += h21.x; a1y += h21.y;
            a2x += h22.x; a2y += h22.y;
        }
        if (r > 3) {
            a0x += h30.x; a0y += h30.y;
            a1x += h31.x; a1y += h31.y;
            a2x += h32.x; a2y += h32.y;
        }
    }
    float2 w0 = ln_relu(a0x, a0y);
    float2 w1 = ln_relu(a1x, a1y);
    float2 w2 = ln_relu(a2x, a2y);
    float2* orow = reinterpret_cast<float2*>(out + v * OUTW);
    orow[64 + lane] = w0;                                   // seg2: cols [128,192)
    float2 d;
    d.x = w0.x - 0.5f * (w1.x + w2.x);
    d.y = w0.y - 0.5f * (w1.y + w2.y);
    orow[160 + lane] = d;                                   // seg5: cols [320,384)
}

// ---------------- launch ----------------
extern "C" void kernel_launch(void* const* d_in, const int* in_sizes, int n_in,
                              void* d_out, int out_size) {
    const float* feature = (const float*)d_in[0];
    const int*   age     = (const int*)d_in[1];
    const int*   src     = (const int*)d_in[2];
    const int*   dst     = (const int*)d_in[3];
    float* out = (float*)d_out;

    const int WARPS_PER_BLOCK = 8;
    const int NODE_BLOCKS = (N_NODES + WARPS_PER_BLOCK - 1) / WARPS_PER_BLOCK;
    const int EDGE_BLOCKS = (N_EDGES + 255) / 256;
    const int NODE_BLOCKS_FLAT = (N_NODES + 255) / 256;

    // zero the histogram via memset (capturable host API, no extra kernel)
    void* count_ptr = nullptr;
    cudaGetSymbolAddress(&count_ptr, g_count);
    cudaMemsetAsync(count_ptr, 0, N_NODES * sizeof(int));

    ln_input_kernel<<<NODE_BLOCKS, WARPS_PER_BLOCK * 32>>>(feature, age, out);
    hist_kernel<<<EDGE_BLOCKS, 256>>>(dst);
    scan_tiles_kernel<<<N_TILES, TILE>>>();
    scan_mid_kernel<<<1, 128>>>();
    scan_add_kernel<<<NODE_BLOCKS_FLAT, 256>>>();
    scatter_kernel<<<EDGE_BLOCKS, 256>>>(src, dst);
    layer1_kernel<<<NODE_BLOCKS, WARPS_PER_BLOCK * 32>>>(age, out);
    layer2_kernel<<<NODE_BLOCKS, WARPS_PER_BLOCK * 32>>>(out);
}

// round 14
// speedup vs baseline: 1.0231x; 1.0231x over previous
#include <cuda_runtime.h>
#include <cuda_fp16.h>

// Problem constants (fixed for this dataset)
#define N_NODES 100000
#define N_EDGES 1200000
#define DIMF    64
#define LN_EPS  1e-5f
#define OUTW    384              // 2*(L+1)*D = 6*64
#define IDMASK  0x1FFFF          // 17 bits for node id (N < 131072)

#define TILE    1024
#define N_TILES ((N_NODES + TILE - 1) / TILE)   // 98

// ---------------- device scratch (static, allowed) ----------------
__device__ int    g_count[N_NODES];            // histogram, then scatter cursor
__device__ int    g_row_ptr[N_NODES + 1];      // CSR by dst
__device__ int    g_col[N_EDGES];              // (age<<17)|src grouped by dst
__device__ int    g_tile_sum[N_TILES];
__device__ int    g_tile_off[N_TILES];
__device__ __half g_hn[N_NODES * DIMF];        // LN(feature), fp16 (gather operand only)
// Interleaved per-node layout: [node][window][dim] -> 384 B contiguous per node
__device__ __half g_h1[N_NODES * 3 * DIMF];    // after layer 1, fp16 (gather operand only)

// ---------------- helpers ----------------
__device__ __forceinline__ void warp_reduce2(float& s, float& sq) {
#pragma unroll
    for (int o = 16; o; o >>= 1) {
        s  += __shfl_xor_sync(0xFFFFFFFFu, s,  o);
        sq += __shfl_xor_sync(0xFFFFFFFFu, sq, o);
    }
}

// LayerNorm(64) + ReLU on a warp-held row (float2 per lane); returns values.
__device__ __forceinline__ float2 ln_relu(float x, float y) {
    float s  = x + y;
    float sq = x * x + y * y;
    warp_reduce2(s, sq);
    float mean = s * (1.0f / 64.0f);
    float var  = fmaxf(sq * (1.0f / 64.0f) - mean * mean, 0.0f);
    float inv  = rsqrtf(var + LN_EPS);
    float2 o;
    o.x = fmaxf((x - mean) * inv, 0.0f);
    o.y = fmaxf((y - mean) * inv, 0.0f);
    return o;
}

// ---------------- kernels ----------------

// hn = LayerNorm(feature). Writes fp16 gather copy + output seg0 / seg3 (fp32).
__global__ void ln_input_kernel(const float* __restrict__ feat,
                                const int* __restrict__ age,
                                float* __restrict__ out) {
    int v    = (blockIdx.x * blockDim.x + threadIdx.x) >> 5;
    int lane = threadIdx.x & 31;
    if (v >= N_NODES) return;
    float2 f = reinterpret_cast<const float2*>(feat)[v * 32 + lane];
    float s  = f.x + f.y;
    float sq = f.x * f.x + f.y * f.y;
    warp_reduce2(s, sq);
    float mean = s * (1.0f / 64.0f);
    float var  = fmaxf(sq * (1.0f / 64.0f) - mean * mean, 0.0f);
    float inv  = rsqrtf(var + LN_EPS);
    float2 o;
    o.x = (f.x - mean) * inv;
    o.y = (f.y - mean) * inv;
    reinterpret_cast<__half2*>(g_hn)[v * 32 + lane] = __floats2half2_rn(o.x, o.y);

    int ag = __ldg(&age[v]);
    float scale = 1.0f - 0.5f * (float)((ag >= 1) + (ag >= 2));
    float2* orow = reinterpret_cast<float2*>(out + v * OUTW);
    orow[lane] = o;                                         // seg0: cols [0,64)
    float2 o3; o3.x = o.x * scale; o3.y = o.y * scale;
    orow[96 + lane] = o3;                                   // seg3: cols [192,256)
}

__global__ void hist_kernel(const int* __restrict__ dst) {
    int i = blockIdx.x * blockDim.x + threadIdx.x;
    if (i < N_EDGES) atomicAdd(&g_count[dst[i]], 1);
}

// --- hierarchical exclusive scan over g_count -> g_row_ptr ---
__global__ void scan_tiles_kernel() {
    __shared__ int warp_sums[32];
    int tile = blockIdx.x;
    int t    = threadIdx.x;           // 0..1023
    int idx  = tile * TILE + t;
    int lane = t & 31;
    int wid  = t >> 5;
    int v = (idx < N_NODES) ? g_count[idx] : 0;
    int incl = v;
#pragma unroll
    for (int o = 1; o < 32; o <<= 1) {
        int n = __shfl_up_sync(0xFFFFFFFFu, incl, o);
        if (lane >= o) incl += n;
    }
    if (lane == 31) warp_sums[wid] = incl;
    __syncthreads();
    if (wid == 0) {
        int ws = warp_sums[lane];
        int wi = ws;
#pragma unroll
        for (int o = 1; o < 32; o <<= 1) {
            int n = __shfl_up_sync(0xFFFFFFFFu, wi, o);
            if (lane >= o) wi += n;
        }
        warp_sums[lane] = wi - ws;   // exclusive warp offsets
        if (lane == 31) g_tile_sum[tile] = wi;   // tile total
    }
    __syncthreads();
    int excl = incl - v + warp_sums[wid];
    if (idx < N_NODES) g_row_ptr[idx] = excl;    // tile-local for now
}

__global__ void scan_mid_kernel() {
    __shared__ int sh[128];
    int t = threadIdx.x;   // 0..127
    int v = (t < N_TILES) ? g_tile_sum[t] : 0;
    sh[t] = v;
    __syncthreads();
#pragma unroll
    for (int o = 1; o < 128; o <<= 1) {
        int add = (t >= o) ? sh[t - o] : 0;
        __syncthreads();
        sh[t] += add;
        __syncthreads();
    }
    if (t < N_TILES) g_tile_off[t] = sh[t] - v;
    if (t == 127) g_row_ptr[N_NODES] = sh[127];
}

__global__ void scan_add_kernel() {
    int idx = blockIdx.x * blockDim.x + threadIdx.x;
    if (idx < N_NODES) {
        int r = g_row_ptr[idx] + g_tile_off[idx / TILE];
        g_row_ptr[idx] = r;
        g_count[idx]   = r;     // cursor for scatter
    }
}

// Scatter with age packed into high bits: col = (age[src]<<17) | src.
__global__ void scatter_kernel(const int* __restrict__ src, const int* __restrict__ dst,
                               const int* __restrict__ age) {
    int i = blockIdx.x * blockDim.x + threadIdx.x;
    if (i < N_EDGES) {
        int s = src[i];
        int pos = atomicAdd(&g_count[dst[i]], 1);
        g_col[pos] = s | (__ldg(&age[s]) << 17);
    }
}

// Layer 1: gather fp16 hn rows, age from packed col, 3 masked accumulators,
// fused LN+ReLU. Writes fp16 g_h1 + output seg1/seg4 (fp32).
__global__ void layer1_kernel(float* __restrict__ out) {
    int v    = (blockIdx.x * blockDim.x + threadIdx.x) >> 5;
    int lane = threadIdx.x & 31;
    if (v >= N_NODES) return;
    int beg = g_row_ptr[v];
    int end = g_row_ptr[v + 1];
    float a0x = 0.f, a0y = 0.f, a1x = 0.f, a1y = 0.f, a2x = 0.f, a2y = 0.f;
    const __half2* hn2 = reinterpret_cast<const __half2*>(g_hn);
    for (int e = beg; e < end; e += 4) {
        int r = end - e;
        int c0 = g_col[e];
        int c1 = (r > 1) ? g_col[e + 1] : c0;
        int c2 = (r > 2) ? g_col[e + 2] : c0;
        int c3 = (r > 3) ? g_col[e + 3] : c0;
        __half2 p0 = hn2[(c0 & IDMASK) * 32 + lane];
        __half2 p1 = hn2[(c1 & IDMASK) * 32 + lane];
        __half2 p2 = hn2[(c2 & IDMASK) * 32 + lane];
        __half2 p3 = hn2[(c3 & IDMASK) * 32 + lane];
        int g0 = c0 >> 17, g1 = c1 >> 17, g2 = c2 >> 17, g3 = c3 >> 17;
        float2 h0 = __half22float2(p0);
        float2 h1 = __half22float2(p1);
        float2 h2 = __half22float2(p2);
        float2 h3 = __half22float2(p3);
        a0x += h0.x; a0y += h0.y;
        if (g0 >= 1) { a1x += h0.x; a1y += h0.y; }
        if (g0 >= 2) { a2x += h0.x; a2y += h0.y; }
        if (r > 1) {
            a0x += h1.x; a0y += h1.y;
            if (g1 >= 1) { a1x += h1.x; a1y += h1.y; }
            if (g1 >= 2) { a2x += h1.x; a2y += h1.y; }
        }
        if (r > 2) {
            a0x += h2.x; a0y += h2.y;
            if (g2 >= 1) { a1x += h2.x; a1y += h2.y; }
            if (g2 >= 2) { a2x += h2.x; a2y += h2.y; }
        }
        if (r > 3) {
            a0x += h3.x; a0y += h3.y;
            if (g3 >= 1) { a1x += h3.x; a1y += h3.y; }
            if (g3 >= 2) { a2x += h3.x; a2y += h3.y; }
        }
    }
    float2 w0 = ln_relu(a0x, a0y);
    float2 w1 = ln_relu(a1x, a1y);
    float2 w2 = ln_relu(a2x, a2y);
    __half2* h1row = reinterpret_cast<__half2*>(&g_h1[v * 3 * DIMF]);
    h1row[lane]      = __floats2half2_rn(w0.x, w0.y);
    h1row[32 + lane] = __floats2half2_rn(w1.x, w1.y);
    h1row[64 + lane] = __floats2half2_rn(w2.x, w2.y);
    float2* orow = reinterpret_cast<float2*>(out + v * OUTW);
    orow[32 + lane] = w0;                                   // seg1: cols [64,128)
    float2 d;
    d.x = w0.x - 0.5f * (w1.x + w2.x);
    d.y = w0.y - 0.5f * (w1.y + w2.y);
    orow[128 + lane] = d;                                   // seg4: cols [256,320)
}

// Layer 2: gather 3 contiguous fp16 window rows per src node (384 B block),
// 4-way batched. Writes output seg2/seg5 (fp32) directly.
__global__ void layer2_kernel(float* __restrict__ out) {
    int v    = (blockIdx.x * blockDim.x + threadIdx.x) >> 5;
    int lane = threadIdx.x & 31;
    if (v >= N_NODES) return;
    int beg = g_row_ptr[v];
    int end = g_row_ptr[v + 1];
    float a0x = 0.f, a0y = 0.f, a1x = 0.f, a1y = 0.f, a2x = 0.f, a2y = 0.f;
    const __half2* h1v = reinterpret_cast<const __half2*>(g_h1);  // node stride = 96 half2
    for (int e = beg; e < end; e += 4) {
        int r = end - e;
        int u0 = g_col[e] & IDMASK;
        int u1 = ((r > 1) ? g_col[e + 1] : g_col[e]) & IDMASK;
        int u2 = ((r > 2) ? g_col[e + 2] : g_col[e]) & IDMASK;
        int u3 = ((r > 3) ? g_col[e + 3] : g_col[e]) & IDMASK;
        int b0 = u0 * 96 + lane;
        int b1 = u1 * 96 + lane;
        int b2 = u2 * 96 + lane;
        int b3 = u3 * 96 + lane;
        __half2 q00 = h1v[b0], q01 = h1v[b0 + 32], q02 = h1v[b0 + 64];
        __half2 q10 = h1v[b1], q11 = h1v[b1 + 32], q12 = h1v[b1 + 64];
        __half2 q20 = h1v[b2], q21 = h1v[b2 + 32], q22 = h1v[b2 + 64];
        __half2 q30 = h1v[b3], q31 = h1v[b3 + 32], q32 = h1v[b3 + 64];
        float2 h00 = __half22float2(q00), h01 = __half22float2(q01), h02 = __half22float2(q02);
        a0x += h00.x; a0y += h00.y;
        a1x += h01.x; a1y += h01.y;
        a2x += h02.x; a2y += h02.y;
        if (r > 1) {
            float2 h10 = __half22float2(q10), h11 = __half22float2(q11), h12 = __half22float2(q12);
            a0x += h10.x; a0y += h10.y;
            a1x += h11.x; a1y += h11.y;
            a2x += h12.x; a2y += h12.y;
        }
        if (r > 2) {
            float2 h20 = __half22float2(q20), h21 = __half22float2(q21), h22 = __half22float2(q22);
            a0x += h20.x; a0y += h20.y;
            a1x += h21.x; a1y += h21.y;
            a2x += h22.x; a2y += h22.y;
        }
        if (r > 3) {
            float2 h30 = __half22float2(q30), h31 = __half22float2(q31), h32 = __half22float2(q32);
            a0x += h30.x; a0y += h30.y;
            a1x += h31.x; a1y += h31.y;
            a2x += h32.x; a2y += h32.y;
        }
    }
    float2 w0 = ln_relu(a0x, a0y);
    float2 w1 = ln_relu(a1x, a1y);
    float2 w2 = ln_relu(a2x, a2y);
    float2* orow = reinterpret_cast<float2*>(out + v * OUTW);
    orow[64 + lane] = w0;                                   // seg2: cols [128,192)
    float2 d;
    d.x = w0.x - 0.5f * (w1.x + w2.x);
    d.y = w0.y - 0.5f * (w1.y + w2.y);
    orow[160 + lane] = d;                                   // seg5: cols [320,384)
}

// ---------------- launch ----------------
extern "C" void kernel_launch(void* const* d_in, const int* in_sizes, int n_in,
                              void* d_out, int out_size) {
    const float* feature = (const float*)d_in[0];
    const int*   age     = (const int*)d_in[1];
    const int*   src     = (const int*)d_in[2];
    const int*   dst     = (const int*)d_in[3];
    float* out = (float*)d_out;

    const int WARPS_PER_BLOCK = 16;   // 512-thread blocks for gather kernels
    const int NODE_BLOCKS = (N_NODES + WARPS_PER_BLOCK - 1) / WARPS_PER_BLOCK;
    const int EDGE_BLOCKS = (N_EDGES + 255) / 256;
    const int NODE_BLOCKS_FLAT = (N_NODES + 255) / 256;

    // zero the histogram via memset (capturable host API, no extra kernel)
    void* count_ptr = nullptr;
    cudaGetSymbolAddress(&count_ptr, g_count);
    cudaMemsetAsync(count_ptr, 0, N_NODES * sizeof(int));

    ln_input_kernel<<<NODE_BLOCKS, WARPS_PER_BLOCK * 32>>>(feature, age, out);
    hist_kernel<<<EDGE_BLOCKS, 256>>>(dst);
    scan_tiles_kernel<<<N_TILES, TILE>>>();
    scan_mid_kernel<<<1, 128>>>();
    scan_add_kernel<<<NODE_BLOCKS_FLAT, 256>>>();
    scatter_kernel<<<EDGE_BLOCKS, 256>>>(src, dst, age);
    layer1_kernel<<<NODE_BLOCKS, WARPS_PER_BLOCK * 32>>>(out);
    layer2_kernel<<<NODE_BLOCKS, WARPS_PER_BLOCK * 32>>>(out);
}

// round 15
// speedup vs baseline: 1.0416x; 1.0181x over previous
#include <cuda_runtime.h>
#include <cuda_fp16.h>

// Problem constants (fixed for this dataset)
#define N_NODES 100000
#define N_EDGES 1200000
#define DIMF    64
#define LN_EPS  1e-5f
#define OUTW    384              // 2*(L+1)*D = 6*64
#define IDMASK  0x1FFFF          // 17 bits for node id (N < 131072)

#define TILE    1024
#define N_TILES ((N_NODES + TILE - 1) / TILE)   // 98

// ---------------- device scratch (static, allowed) ----------------
__device__ int    g_count[N_NODES];            // histogram, then scatter cursor
__device__ int    g_row_ptr[N_NODES + 1];      // CSR by dst
__device__ int    g_col[N_EDGES];              // (age<<17)|src grouped by dst
__device__ int    g_tile_agg[N_TILES];         // per-tile aggregate (lookback scan)
__device__ int    g_tile_flag[N_TILES];        // publication flags (lookback scan)
__device__ __half g_hn[N_NODES * DIMF];        // LN(feature), fp16 (gather operand only)
// Interleaved per-node layout: [node][window][dim] -> 384 B contiguous per node
__device__ __half g_h1[N_NODES * 3 * DIMF];    // after layer 1, fp16 (gather operand only)

// ---------------- helpers ----------------
__device__ __forceinline__ void warp_reduce2(float& s, float& sq) {
#pragma unroll
    for (int o = 16; o; o >>= 1) {
        s  += __shfl_xor_sync(0xFFFFFFFFu, s,  o);
        sq += __shfl_xor_sync(0xFFFFFFFFu, sq, o);
    }
}

// LayerNorm(64) + ReLU on a warp-held row (float2 per lane); returns values.
__device__ __forceinline__ float2 ln_relu(float x, float y) {
    float s  = x + y;
    float sq = x * x + y * y;
    warp_reduce2(s, sq);
    float mean = s * (1.0f / 64.0f);
    float var  = fmaxf(sq * (1.0f / 64.0f) - mean * mean, 0.0f);
    float inv  = rsqrtf(var + LN_EPS);
    float2 o;
    o.x = fmaxf((x - mean) * inv, 0.0f);
    o.y = fmaxf((y - mean) * inv, 0.0f);
    return o;
}

// ---------------- kernels ----------------

// Fused: hn = LayerNorm(feature) (+ output seg0/seg3) AND dst histogram AND flag reset.
// One warp per node for the LN part; one thread per edge for the hist part.
__global__ void ln_hist_kernel(const float* __restrict__ feat,
                               const int* __restrict__ age,
                               const int* __restrict__ dst,
                               float* __restrict__ out) {
    int gid  = blockIdx.x * blockDim.x + threadIdx.x;
    int v    = gid >> 5;
    int lane = threadIdx.x & 31;

    // reset lookback flags for this invocation (read by scan_kernel, next launch)
    if (gid < N_TILES) g_tile_flag[gid] = 0;

    // histogram part: one edge per thread (grid is 3.2M threads > 1.2M edges)
    if (gid < N_EDGES) atomicAdd(&g_count[dst[gid]], 1);

    // LN part: one warp per node
    if (v >= N_NODES) return;
    float2 f = reinterpret_cast<const float2*>(feat)[v * 32 + lane];
    float s  = f.x + f.y;
    float sq = f.x * f.x + f.y * f.y;
    warp_reduce2(s, sq);
    float mean = s * (1.0f / 64.0f);
    float var  = fmaxf(sq * (1.0f / 64.0f) - mean * mean, 0.0f);
    float inv  = rsqrtf(var + LN_EPS);
    float2 o;
    o.x = (f.x - mean) * inv;
    o.y = (f.y - mean) * inv;
    reinterpret_cast<__half2*>(g_hn)[v * 32 + lane] = __floats2half2_rn(o.x, o.y);

    int ag = __ldg(&age[v]);
    float scale = 1.0f - 0.5f * (float)((ag >= 1) + (ag >= 2));
    float2* orow = reinterpret_cast<float2*>(out + v * OUTW);
    orow[lane] = o;                                         // seg0: cols [0,64)
    float2 o3; o3.x = o.x * scale; o3.y = o.y * scale;
    orow[96 + lane] = o3;                                   // seg3: cols [192,256)
}

// Single-kernel exclusive scan with decoupled lookback.
// 98 blocks (all resident on 148 SMs -> spin is deadlock-free).
__global__ void scan_kernel() {
    __shared__ int warp_sums[32];
    __shared__ int s_base;
    int tile = blockIdx.x;
    int t    = threadIdx.x;           // 0..1023
    int idx  = tile * TILE + t;
    int lane = t & 31;
    int wid  = t >> 5;
    int v = (idx < N_NODES) ? g_count[idx] : 0;
    // warp inclusive scan
    int incl = v;
#pragma unroll
    for (int o = 1; o < 32; o <<= 1) {
        int n = __shfl_up_sync(0xFFFFFFFFu, incl, o);
        if (lane >= o) incl += n;
    }
    if (lane == 31) warp_sums[wid] = incl;
    __syncthreads();
    if (wid == 0) {
        int ws = warp_sums[lane];
        int wi = ws;
#pragma unroll
        for (int o = 1; o < 32; o <<= 1) {
            int n = __shfl_up_sync(0xFFFFFFFFu, wi, o);
            if (lane >= o) wi += n;
        }
        warp_sums[lane] = wi - ws;   // exclusive warp offsets
        if (lane == 31) {
            g_tile_agg[tile] = wi;   // publish tile aggregate
            __threadfence();
            atomicExch(&g_tile_flag[tile], 1);
        }
    }
    __syncthreads();
    // lookback: warp 0 sums aggregates of all predecessor tiles
    if (wid == 0) {
        int base = 0;
        for (int p = lane; p < tile; p += 32) {
            while (atomicAdd(&g_tile_flag[p], 0) == 0) { }
            base += atomicAdd(&g_tile_agg[p], 0);   // atomic read: L2-coherent with publisher
        }
#pragma unroll
        for (int o = 16; o; o >>= 1) base += __shfl_xor_sync(0xFFFFFFFFu, base, o);
        if (lane == 0) s_base = base;
    }
    __syncthreads();
    int excl = s_base + incl - v + warp_sums[wid];
    if (idx < N_NODES) {
        g_row_ptr[idx] = excl;
        g_count[idx]   = excl;       // cursor for scatter
    }
    if (tile == N_TILES - 1 && t == 0)
        g_row_ptr[N_NODES] = s_base + g_tile_agg[tile];   // own-block global write, ordered by syncthreads
}

// Scatter with age packed into high bits: col = (age[src]<<17) | src.
__global__ void scatter_kernel(const int* __restrict__ src, const int* __restrict__ dst,
                               const int* __restrict__ age) {
    int i = blockIdx.x * blockDim.x + threadIdx.x;
    if (i < N_EDGES) {
        int s = src[i];
        int pos = atomicAdd(&g_count[dst[i]], 1);
        g_col[pos] = s | (__ldg(&age[s]) << 17);
    }
}

// Layer 1: gather fp16 hn rows, age from packed col, 3 masked accumulators,
// fused LN+ReLU. Writes fp16 g_h1 + output seg1/seg4 (fp32).
__global__ void layer1_kernel(float* __restrict__ out) {
    int v    = (blockIdx.x * blockDim.x + threadIdx.x) >> 5;
    int lane = threadIdx.x & 31;
    if (v >= N_NODES) return;
    int beg = g_row_ptr[v];
    int end = g_row_ptr[v + 1];
    float a0x = 0.f, a0y = 0.f, a1x = 0.f, a1y = 0.f, a2x = 0.f, a2y = 0.f;
    const __half2* hn2 = reinterpret_cast<const __half2*>(g_hn);
    for (int e = beg; e < end; e += 4) {
        int r = end - e;
        int c0 = g_col[e];
        int c1 = (r > 1) ? g_col[e + 1] : c0;
        int c2 = (r > 2) ? g_col[e + 2] : c0;
        int c3 = (r > 3) ? g_col[e + 3] : c0;
        __half2 p0 = hn2[(c0 & IDMASK) * 32 + lane];
        __half2 p1 = hn2[(c1 & IDMASK) * 32 + lane];
        __half2 p2 = hn2[(c2 & IDMASK) * 32 + lane];
        __half2 p3 = hn2[(c3 & IDMASK) * 32 + lane];
        int g0 = c0 >> 17, g1 = c1 >> 17, g2 = c2 >> 17, g3 = c3 >> 17;
        float2 h0 = __half22float2(p0);
        float2 h1 = __half22float2(p1);
        float2 h2 = __half22float2(p2);
        float2 h3 = __half22float2(p3);
        a0x += h0.x; a0y += h0.y;
        if (g0 >= 1) { a1x += h0.x; a1y += h0.y; }
        if (g0 >= 2) { a2x += h0.x; a2y += h0.y; }
        if (r > 1) {
            a0x += h1.x; a0y += h1.y;
            if (g1 >= 1) { a1x += h1.x; a1y += h1.y; }
            if (g1 >= 2) { a2x += h1.x; a2y += h1.y; }
        }
        if (r > 2) {
            a0x += h2.x; a0y += h2.y;
            if (g2 >= 1) { a1x += h2.x; a1y += h2.y; }
            if (g2 >= 2) { a2x += h2.x; a2y += h2.y; }
        }
        if (r > 3) {
            a0x += h3.x; a0y += h3.y;
            if (g3 >= 1) { a1x += h3.x; a1y += h3.y; }
            if (g3 >= 2) { a2x += h3.x; a2y += h3.y; }
        }
    }
    float2 w0 = ln_relu(a0x, a0y);
    float2 w1 = ln_relu(a1x, a1y);
    float2 w2 = ln_relu(a2x, a2y);
    __half2* h1row = reinterpret_cast<__half2*>(&g_h1[v * 3 * DIMF]);
    h1row[lane]      = __floats2half2_rn(w0.x, w0.y);
    h1row[32 + lane] = __floats2half2_rn(w1.x, w1.y);
    h1row[64 + lane] = __floats2half2_rn(w2.x, w2.y);
    float2* orow = reinterpret_cast<float2*>(out + v * OUTW);
    orow[32 + lane] = w0;                                   // seg1: cols [64,128)
    float2 d;
    d.x = w0.x - 0.5f * (w1.x + w2.x);
    d.y = w0.y - 0.5f * (w1.y + w2.y);
    orow[128 + lane] = d;                                   // seg4: cols [256,320)
}

// Layer 2: gather 3 contiguous fp16 window rows per src node (384 B block),
// 4-way batched. Writes output seg2/seg5 (fp32) directly.
__global__ void layer2_kernel(float* __restrict__ out) {
    int v    = (blockIdx.x * blockDim.x + threadIdx.x) >> 5;
    int lane = threadIdx.x & 31;
    if (v >= N_NODES) return;
    int beg = g_row_ptr[v];
    int end = g_row_ptr[v + 1];
    float a0x = 0.f, a0y = 0.f, a1x = 0.f, a1y = 0.f, a2x = 0.f, a2y = 0.f;
    const __half2* h1v = reinterpret_cast<const __half2*>(g_h1);  // node stride = 96 half2
    for (int e = beg; e < end; e += 4) {
        int r = end - e;
        int u0 = g_col[e] & IDMASK;
        int u1 = ((r > 1) ? g_col[e + 1] : g_col[e]) & IDMASK;
        int u2 = ((r > 2) ? g_col[e + 2] : g_col[e]) & IDMASK;
        int u3 = ((r > 3) ? g_col[e + 3] : g_col[e]) & IDMASK;
        int b0 = u0 * 96 + lane;
        int b1 = u1 * 96 + lane;
        int b2 = u2 * 96 + lane;
        int b3 = u3 * 96 + lane;
        __half2 q00 = h1v[b0], q01 = h1v[b0 + 32], q02 = h1v[b0 + 64];
        __half2 q10 = h1v[b1], q11 = h1v[b1 + 32], q12 = h1v[b1 + 64];
        __half2 q20 = h1v[b2], q21 = h1v[b2 + 32], q22 = h1v[b2 + 64];
        __half2 q30 = h1v[b3], q31 = h1v[b3 + 32], q32 = h1v[b3 + 64];
        float2 h00 = __half22float2(q00), h01 = __half22float2(q01), h02 = __half22float2(q02);
        a0x += h00.x; a0y += h00.y;
        a1x += h01.x; a1y += h01.y;
        a2x += h02.x; a2y += h02.y;
        if (r > 1) {
            float2 h10 = __half22float2(q10), h11 = __half22float2(q11), h12 = __half22float2(q12);
            a0x += h10.x; a0y += h10.y;
            a1x += h11.x; a1y += h11.y;
            a2x += h12.x; a2y += h12.y;
        }
        if (r > 2) {
            float2 h20 = __half22float2(q20), h21 = __half22float2(q21), h22 = __half22float2(q22);
            a0x += h20.x; a0y += h20.y;
            a1x += h21.x; a1y += h21.y;
            a2x += h22.x; a2y += h22.y;
        }
        if (r > 3) {
            float2 h30 = __half22float2(q30), h31 = __half22float2(q31), h32 = __half22float2(q32);
            a0x += h30.x; a0y += h30.y;
            a1x += h31.x; a1y += h31.y;
            a2x += h32.x; a2y += h32.y;
        }
    }
    float2 w0 = ln_relu(a0x, a0y);
    float2 w1 = ln_relu(a1x, a1y);
    float2 w2 = ln_relu(a2x, a2y);
    float2* orow = reinterpret_cast<float2*>(out + v * OUTW);
    orow[64 + lane] = w0;                                   // seg2: cols [128,192)
    float2 d;
    d.x = w0.x - 0.5f * (w1.x + w2.x);
    d.y = w0.y - 0.5f * (w1.y + w2.y);
    orow[160 + lane] = d;                                   // seg5: cols [320,384)
}

// ---------------- launch ----------------
extern "C" void kernel_launch(void* const* d_in, const int* in_sizes, int n_in,
                              void* d_out, int out_size) {
    const float* feature = (const float*)d_in[0];
    const int*   age     = (const int*)d_in[1];
    const int*   src     = (const int*)d_in[2];
    const int*   dst     = (const int*)d_in[3];
    float* out = (float*)d_out;

    const int WARPS_PER_BLOCK = 16;   // 512-thread blocks
    const int NODE_BLOCKS = (N_NODES + WARPS_PER_BLOCK - 1) / WARPS_PER_BLOCK;
    const int EDGE_BLOCKS = (N_EDGES + 255) / 256;

    // zero the histogram via memset (capturable host API)
    void* count_ptr = nullptr;
    cudaGetSymbolAddress(&count_ptr, g_count);
    cudaMemsetAsync(count_ptr, 0, N_NODES * sizeof(int));

    // 6250 blocks x 512 threads = 3.2M threads: covers LN (warp/node) + hist (thread/edge)
    ln_hist_kernel<<<NODE_BLOCKS, WARPS_PER_BLOCK * 32>>>(feature, age, dst, out);
    scan_kernel<<<N_TILES, TILE>>>();
    scatter_kernel<<<EDGE_BLOCKS, 256>>>(src, dst, age);
    layer1_kernel<<<NODE_BLOCKS, WARPS_PER_BLOCK * 32>>>(out);
    layer2_kernel<<<NODE_BLOCKS, WARPS_PER_BLOCK * 32>>>(out);
}